// round 5
// baseline (speedup 1.0000x reference)
#include <cuda_runtime.h>

#define NP 1000000
#define NPIL 30000

typedef unsigned long long ull;

__device__ __forceinline__ ull pack2(float lo, float hi) {
    ull r; asm("mov.b64 %0,{%1,%2};" : "=l"(r) : "f"(lo), "f"(hi)); return r;
}
__device__ __forceinline__ void unpack2(ull v, float& lo, float& hi) {
    asm("mov.b64 {%0,%1},%2;" : "=f"(lo), "=f"(hi) : "l"(v));
}
__device__ __forceinline__ ull ffma2(ull a, ull b, ull c) {
    ull d; asm("fma.rn.f32x2 %0,%1,%2,%3;" : "=l"(d) : "l"(a), "l"(b), "l"(c)); return d;
}
__device__ __forceinline__ ull fadd2(ull a, ull b) {
    ull d; asm("add.rn.f32x2 %0,%1,%2;" : "=l"(d) : "l"(a), "l"(b)); return d;
}

// ---------------- scratch ----------------
__device__ float d_W1f[7 * 32];
__device__ float d_t1[32];
__device__ float d_W2f[64 * 32];
__device__ float d_t2[32];
__device__ int   d_count[NPIL];
__device__ int   d_offset[NPIL];
__device__ int   d_galloc;
__device__ int   d_pos[NP];                              // rank of point within its pillar
__device__ int   d_idx[NP];                              // pillar-grouped point indices
__device__ __align__(16) float d_hs[(size_t)NP * 32];    // h rows in POINT order (128 MB)

// ---------------- init: zero counters + fold BN into weights ----------------
__global__ void k_init(const float* __restrict__ W1, const float* __restrict__ g1,
                       const float* __restrict__ b1, const float* __restrict__ m1,
                       const float* __restrict__ v1, const float* __restrict__ W2,
                       const float* __restrict__ g2, const float* __restrict__ b2,
                       const float* __restrict__ m2, const float* __restrict__ v2) {
    int i = blockIdx.x * blockDim.x + threadIdx.x;
    if (i < NPIL) d_count[i] = 0;
    if (i == 0) d_galloc = 0;
    if (blockIdx.x == 0 && threadIdx.x < 32) {
        int j = threadIdx.x;
        float s1 = g1[j] * rsqrtf(v1[j] + 1e-3f);
        d_t1[j] = b1[j] - m1[j] * s1;
        for (int k = 0; k < 7; k++) d_W1f[k * 32 + j] = W1[k * 32 + j] * s1;
        float s2 = g2[j] * rsqrtf(v2[j] + 1e-3f);
        d_t2[j] = b2[j] - m2[j] * s2;
        for (int k = 0; k < 64; k++) d_W2f[k * 32 + j] = W2[k * 32 + j] * s2;
    }
}

// ---------------- histogram + per-point rank (int4 vectorized) ----------------
__global__ void k_hist(const int* __restrict__ unq) {
    int i = blockIdx.x * blockDim.x + threadIdx.x;
    if (i < NP / 4) {
        int4 v = ((const int4*)unq)[i];
        int4 r;
        r.x = atomicAdd(&d_count[v.x], 1);
        r.y = atomicAdd(&d_count[v.y], 1);
        r.z = atomicAdd(&d_count[v.z], 1);
        r.w = atomicAdd(&d_count[v.w], 1);
        ((int4*)d_pos)[i] = r;
    }
}

// ---------------- segment allocation: block scan + one global atomic per block ----------------
__global__ __launch_bounds__(256) void k_alloc() {
    __shared__ int wsum[8], wpre[8], sbase;
    int t = threadIdx.x, lane = t & 31, w = t >> 5;
    int i = blockIdx.x * 256 + t;
    int c = (i < NPIL) ? d_count[i] : 0;
    int incl = c;
#pragma unroll
    for (int d = 1; d < 32; d <<= 1) {
        int v = __shfl_up_sync(0xffffffffu, incl, d);
        if (lane >= d) incl += v;
    }
    if (lane == 31) wsum[w] = incl;
    __syncthreads();
    if (w == 0 && lane < 8) {
        int s = wsum[lane];
        int inc = s;
#pragma unroll
        for (int d = 1; d < 8; d <<= 1) {
            int v = __shfl_up_sync(0xffu, inc, d);
            if (lane >= d) inc += v;
        }
        wpre[lane] = inc - s;
        if (lane == 7) sbase = atomicAdd(&d_galloc, inc);
    }
    __syncthreads();
    if (i < NPIL) d_offset[i] = sbase + wpre[w] + (incl - c);
}

// ---------------- scatter point indices into pillar-grouped order (4B writes only) ----------------
__global__ void k_sidx(const int* __restrict__ unq) {
    int i = blockIdx.x * blockDim.x + threadIdx.x;
    if (i < NP / 4) {
        int4 u = ((const int4*)unq)[i];
        int4 r = ((const int4*)d_pos)[i];
        int b = i * 4;
        d_idx[d_offset[u.x] + r.x] = b + 0;
        d_idx[d_offset[u.y] + r.y] = b + 1;
        d_idx[d_offset[u.z] + r.z] = b + 2;
        d_idx[d_offset[u.w] + r.w] = b + 3;
    }
}

// ---------------- pass 1: h = relu(feat @ W1f + t1), COALESCED point-order store ----------------
// Staging: ull rows, stride 17 ulls (136B) -> all smem accesses are 8B-aligned
// STS.64/LDS.64, conflict-free in both write and copy-out phases.
__global__ __launch_bounds__(256) void k_pass1(const float* __restrict__ pts,
                                               const float* __restrict__ fc) {
    __shared__ ull swp[112];            // 7 x 16 packed weight pairs
    __shared__ ull st2[16];
    __shared__ ull sh[256 * 17];        // 34 KB staging
    int t = threadIdx.x;
    if (t < 112) { float2 w = ((const float2*)d_W1f)[t]; swp[t] = pack2(w.x, w.y); }
    if (t < 16)  { float2 v = ((const float2*)d_t1)[t];  st2[t] = pack2(v.x, v.y); }
    __syncthreads();

    int i = blockIdx.x * 256 + t;
    if (i < NP) {
        float f[7];
        f[0] = fc[i * 3 + 0];
        f[1] = fc[i * 3 + 1];
        f[2] = fc[i * 3 + 2];
        f[3] = pts[i * 5 + 1];
        f[4] = pts[i * 5 + 2];
        f[5] = pts[i * 5 + 3];
        f[6] = pts[i * 5 + 4];

        ull h2[16];
#pragma unroll
        for (int j = 0; j < 16; j++) h2[j] = st2[j];
#pragma unroll
        for (int k = 0; k < 7; k++) {
            ull fk = pack2(f[k], f[k]);
#pragma unroll
            for (int j = 0; j < 16; j++) h2[j] = ffma2(swp[k * 16 + j], fk, h2[j]);
        }
        // relu + stage (STS.64, conflict-free: bank = 2*t + q*? distinct per phase)
        ull* myrow = &sh[t * 17];
#pragma unroll
        for (int q = 0; q < 16; q++) {
            float x0, x1;
            unpack2(h2[q], x0, x1);
            myrow[q] = pack2(fmaxf(x0, 0.f), fmaxf(x1, 0.f));
        }
    }
    __syncthreads();

    // cooperative coalesced copy-out: 4096 ulls (32 KB) per block
    size_t base = (size_t)blockIdx.x * 4096;           // in ull units
    size_t lim = (size_t)NP * 16;
    ull* dst = reinterpret_cast<ull*>(d_hs);
#pragma unroll
    for (int g = 0; g < 4096; g += 256) {
        size_t o = base + g + t;
        if (o < lim) {
            int r = (g + t) >> 4, c = (g + t) & 15;
            dst[o] = sh[r * 17 + c];
        }
    }
}

// ---------------- pass 2: warp/pillar, idx-gathered rows, smem weights ----------------
__global__ __launch_bounds__(256) void k_pillar(float* __restrict__ out) {
    __shared__ ulonglong2 sWaP[16][32];      // packed {w,w} pairs for W2a (8 KB)
    __shared__ float sWb[32 * 32];           // W2b (4 KB)
    __shared__ float sT2[32];
    __shared__ __align__(16) ull shrow[8][32];
    __shared__ float shm[8][32];

    int t = threadIdx.x;
    for (int q = t; q < 1024; q += 256) {
        int k = q >> 5, j = q & 31;
        float w = d_W2f[k * 32 + j];
        ull pw = pack2(w, w);
        if (k & 1) sWaP[k >> 1][j].y = pw; else sWaP[k >> 1][j].x = pw;
        sWb[q] = d_W2f[(k + 32) * 32 + j];
    }
    if (t < 32) sT2[t] = d_t2[t];
    __syncthreads();

    int warp = t >> 5;
    int j = t & 31;
    int p = blockIdx.x * 8 + warp;                 // 3750 * 8 == 30000 exact
    int off = d_offset[p];
    int cnt = d_count[p];
    if (cnt == 0) { out[p * 32 + j] = 0.f; return; }
    const int* ip = d_idx + off;

    // sweep 1: channel sums over gathered rows (full 128B line per row)
    float s0 = 0.f, s1 = 0.f, s2 = 0.f, s3 = 0.f;
    for (int rb = 0; rb < cnt; rb += 32) {
        int lim = min(32, cnt - rb);
        int myidx = (j < lim) ? ip[rb + j] : 0;
        int u = 0;
        for (; u + 4 <= lim; u += 4) {
            int r0 = __shfl_sync(0xffffffffu, myidx, u + 0);
            int r1 = __shfl_sync(0xffffffffu, myidx, u + 1);
            int r2 = __shfl_sync(0xffffffffu, myidx, u + 2);
            int r3 = __shfl_sync(0xffffffffu, myidx, u + 3);
            s0 += d_hs[(size_t)r0 * 32 + j];
            s1 += d_hs[(size_t)r1 * 32 + j];
            s2 += d_hs[(size_t)r2 * 32 + j];
            s3 += d_hs[(size_t)r3 * 32 + j];
        }
        for (; u < lim; u++) {
            int r0 = __shfl_sync(0xffffffffu, myidx, u);
            s0 += d_hs[(size_t)r0 * 32 + j];
        }
    }
    float mean = ((s0 + s1) + (s2 + s3)) / (float)cnt;

    // pm_j = t2_j + mean . W2b[:,j]
    shm[warp][j] = mean;
    __syncwarp();
    float pm = sT2[j];
#pragma unroll
    for (int k = 0; k < 32; k++) pm = fmaf(shm[warp][k], sWb[k * 32 + j], pm);
    ull pm2 = pack2(pm, pm);
    ull z2 = pack2(0.f, 0.f);

    // sweep 2: two rows per iteration via fma.rn.f32x2 (rows L1-hot after sweep 1)
    float maxv = 0.f;
    const ull* row = shrow[warp];
    for (int rb = 0; rb < cnt; rb += 32) {
        int lim = min(32, cnt - rb);
        int myidx = (j < lim) ? ip[rb + j] : 0;
        for (int u = 0; u < lim; u += 2) {
            int rA = __shfl_sync(0xffffffffu, myidx, u);
            int rB = __shfl_sync(0xffffffffu, myidx, (u + 1 < lim) ? u + 1 : u);
            float a0 = d_hs[(size_t)rA * 32 + j];
            float a1 = d_hs[(size_t)rB * 32 + j];
            shrow[warp][j] = pack2(a0, a1);
            __syncwarp();
            ull acc0 = pm2, acc1 = z2, acc2 = z2, acc3 = z2;
#pragma unroll
            for (int k2 = 0; k2 < 16; k2 += 2) {
                ulonglong2 r01 = *reinterpret_cast<const ulonglong2*>(&row[k2 * 2 + 0]);
                ulonglong2 r23 = *reinterpret_cast<const ulonglong2*>(&row[k2 * 2 + 2]);
                ulonglong2 w01 = sWaP[k2 + 0][j];
                ulonglong2 w23 = sWaP[k2 + 1][j];
                acc0 = ffma2(r01.x, w01.x, acc0);
                acc1 = ffma2(r01.y, w01.y, acc1);
                acc2 = ffma2(r23.x, w23.x, acc2);
                acc3 = ffma2(r23.y, w23.y, acc3);
            }
            __syncwarp();
            ull tt = fadd2(fadd2(acc0, acc1), fadd2(acc2, acc3));
            float lo, hi;
            unpack2(tt, lo, hi);
            maxv = fmaxf(maxv, fmaxf(lo, hi));
        }
    }
    out[p * 32 + j] = maxv;
}

// ---------------- launch ----------------
extern "C" void kernel_launch(void* const* d_in, const int* in_sizes, int n_in,
                              void* d_out, int out_size) {
    const float* points   = (const float*)d_in[0];
    const float* f_center = (const float*)d_in[1];
    const int*   unq      = (const int*)d_in[2];
    const float* W1 = (const float*)d_in[3];
    const float* g1 = (const float*)d_in[4];
    const float* b1 = (const float*)d_in[5];
    const float* m1 = (const float*)d_in[6];
    const float* v1 = (const float*)d_in[7];
    const float* W2 = (const float*)d_in[8];
    const float* g2 = (const float*)d_in[9];
    const float* b2 = (const float*)d_in[10];
    const float* m2 = (const float*)d_in[11];
    const float* v2 = (const float*)d_in[12];

    k_init<<<(NPIL + 255) / 256, 256>>>(W1, g1, b1, m1, v1, W2, g2, b2, m2, v2);
    k_hist<<<(NP / 4 + 255) / 256, 256>>>(unq);
    k_alloc<<<(NPIL + 255) / 256, 256>>>();
    k_sidx<<<(NP / 4 + 255) / 256, 256>>>(unq);
    k_pass1<<<(NP + 255) / 256, 256>>>(points, f_center);
    k_pillar<<<NPIL / 8, 256>>>((float*)d_out);
}

// round 6
// speedup vs baseline: 1.4196x; 1.4196x over previous
#include <cuda_runtime.h>

#define NP 1000000
#define NPIL 30000

typedef unsigned long long ull;

__device__ __forceinline__ ull pack2(float lo, float hi) {
    ull r; asm("mov.b64 %0,{%1,%2};" : "=l"(r) : "f"(lo), "f"(hi)); return r;
}
__device__ __forceinline__ void unpack2(ull v, float& lo, float& hi) {
    asm("mov.b64 {%0,%1},%2;" : "=f"(lo), "=f"(hi) : "l"(v));
}
__device__ __forceinline__ ull ffma2(ull a, ull b, ull c) {
    ull d; asm("fma.rn.f32x2 %0,%1,%2,%3;" : "=l"(d) : "l"(a), "l"(b), "l"(c)); return d;
}

// ---------------- scratch ----------------
__device__ float d_W1f[7 * 32];
__device__ float d_t1[32];
__device__ float d_W2f[64 * 32];
__device__ float d_t2[32];
__device__ int   d_count[NPIL];
__device__ int   d_offset[NPIL];
__device__ int   d_galloc;
__device__ int   d_pos[NP];                            // rank of point within its pillar
__device__ int   d_idx[NP];                            // pillar-grouped point indices
__device__ __align__(16) float d_ha[(size_t)NP * 64];  // per point: [h(32) | a(32)] (256 MB)

// ---------------- init: zero counters + fold BN into weights ----------------
__global__ void k_init(const float* __restrict__ W1, const float* __restrict__ g1,
                       const float* __restrict__ b1, const float* __restrict__ m1,
                       const float* __restrict__ v1, const float* __restrict__ W2,
                       const float* __restrict__ g2, const float* __restrict__ b2,
                       const float* __restrict__ m2, const float* __restrict__ v2) {
    int i = blockIdx.x * blockDim.x + threadIdx.x;
    if (i < NPIL) d_count[i] = 0;
    if (i == 0) d_galloc = 0;
    if (blockIdx.x == 0 && threadIdx.x < 32) {
        int j = threadIdx.x;
        float s1 = g1[j] * rsqrtf(v1[j] + 1e-3f);
        d_t1[j] = b1[j] - m1[j] * s1;
        for (int k = 0; k < 7; k++) d_W1f[k * 32 + j] = W1[k * 32 + j] * s1;
        float s2 = g2[j] * rsqrtf(v2[j] + 1e-3f);
        d_t2[j] = b2[j] - m2[j] * s2;
        for (int k = 0; k < 64; k++) d_W2f[k * 32 + j] = W2[k * 32 + j] * s2;
    }
}

// ---------------- histogram + per-point rank (int4 vectorized) ----------------
__global__ void k_hist(const int* __restrict__ unq) {
    int i = blockIdx.x * blockDim.x + threadIdx.x;
    if (i < NP / 4) {
        int4 v = ((const int4*)unq)[i];
        int4 r;
        r.x = atomicAdd(&d_count[v.x], 1);
        r.y = atomicAdd(&d_count[v.y], 1);
        r.z = atomicAdd(&d_count[v.z], 1);
        r.w = atomicAdd(&d_count[v.w], 1);
        ((int4*)d_pos)[i] = r;
    }
}

// ---------------- segment allocation: block scan + one global atomic per block ----------------
__global__ __launch_bounds__(256) void k_alloc() {
    __shared__ int wsum[8], wpre[8], sbase;
    int t = threadIdx.x, lane = t & 31, w = t >> 5;
    int i = blockIdx.x * 256 + t;
    int c = (i < NPIL) ? d_count[i] : 0;
    int incl = c;
#pragma unroll
    for (int d = 1; d < 32; d <<= 1) {
        int v = __shfl_up_sync(0xffffffffu, incl, d);
        if (lane >= d) incl += v;
    }
    if (lane == 31) wsum[w] = incl;
    __syncthreads();
    if (w == 0 && lane < 8) {
        int s = wsum[lane];
        int inc = s;
#pragma unroll
        for (int d = 1; d < 8; d <<= 1) {
            int v = __shfl_up_sync(0xffu, inc, d);
            if (lane >= d) inc += v;
        }
        wpre[lane] = inc - s;
        if (lane == 7) sbase = atomicAdd(&d_galloc, inc);
    }
    __syncthreads();
    if (i < NPIL) d_offset[i] = sbase + wpre[w] + (incl - c);
}

// ---------------- scatter point indices into pillar-grouped order (4B writes only) ----------------
__global__ void k_sidx(const int* __restrict__ unq) {
    int i = blockIdx.x * blockDim.x + threadIdx.x;
    if (i < NP / 4) {
        int4 u = ((const int4*)unq)[i];
        int4 r = ((const int4*)d_pos)[i];
        int b = i * 4;
        d_idx[d_offset[u.x] + r.x] = b + 0;
        d_idx[d_offset[u.y] + r.y] = b + 1;
        d_idx[d_offset[u.z] + r.z] = b + 2;
        d_idx[d_offset[u.w] + r.w] = b + 3;
    }
}

// ---------------- pass 1: h = relu(feat@W1f+t1); a = h@W2a + t2; store [h|a] coalesced ----------
// smem staging: 33-ull stride rows (8B-aligned, conflict-free at the 64-bit floor)
__global__ __launch_bounds__(128) void k_pass1(const float* __restrict__ pts,
                                               const float* __restrict__ fc) {
    __shared__ ull swp[112];            // W1f packed pairs (7 x 16)
    __shared__ ull st1[16];
    __shared__ ull swa[512];            // W2a packed pairs (32 x 16), 4 KB
    __shared__ ull st2[16];
    __shared__ ull sh[128 * 33];        // 33.8 KB staging
    int t = threadIdx.x;
    for (int q = t; q < 112; q += 128) { float2 w = ((const float2*)d_W1f)[q]; swp[q] = pack2(w.x, w.y); }
    for (int q = t; q < 512; q += 128) { float2 w = ((const float2*)d_W2f)[q]; swa[q] = pack2(w.x, w.y); }
    if (t < 16) { float2 v = ((const float2*)d_t1)[t]; st1[t] = pack2(v.x, v.y); }
    else if (t < 32) { float2 v = ((const float2*)d_t2)[t - 16]; st2[t - 16] = pack2(v.x, v.y); }
    __syncthreads();

    int i = blockIdx.x * 128 + t;
    if (i < NP) {
        float f[7];
        f[0] = fc[i * 3 + 0];
        f[1] = fc[i * 3 + 1];
        f[2] = fc[i * 3 + 2];
        f[3] = pts[i * 5 + 1];
        f[4] = pts[i * 5 + 2];
        f[5] = pts[i * 5 + 3];
        f[6] = pts[i * 5 + 4];

        // h = feat @ W1f + t1 (packed)
        ull h2[16];
#pragma unroll
        for (int j = 0; j < 16; j++) h2[j] = st1[j];
#pragma unroll
        for (int k = 0; k < 7; k++) {
            ull fk = pack2(f[k], f[k]);
#pragma unroll
            for (int j = 0; j < 16; j++) h2[j] = ffma2(swp[k * 16 + j], fk, h2[j]);
        }
        // relu -> scalar h
        float hr[32];
#pragma unroll
        for (int j = 0; j < 16; j++) {
            float lo, hi;
            unpack2(h2[j], lo, hi);
            hr[2 * j] = fmaxf(lo, 0.f);
            hr[2 * j + 1] = fmaxf(hi, 0.f);
        }
        // a = h @ W2a + t2 (packed, smem-broadcast weights)
        ull a2[16];
#pragma unroll
        for (int j = 0; j < 16; j++) a2[j] = st2[j];
#pragma unroll
        for (int k = 0; k < 32; k++) {
            ull fk = pack2(hr[k], hr[k]);
            const ull* wrow = &swa[k * 16];
#pragma unroll
            for (int j = 0; j < 16; j++) a2[j] = ffma2(wrow[j], fk, a2[j]);
        }
        // stage row: [h pairs | a pairs]
        ull* myrow = &sh[t * 33];
#pragma unroll
        for (int q = 0; q < 16; q++) myrow[q] = pack2(hr[2 * q], hr[2 * q + 1]);
#pragma unroll
        for (int q = 0; q < 16; q++) myrow[16 + q] = a2[q];
    }
    __syncthreads();

    // coalesced copy-out: 128 rows x 32 ulls = 4096 ulls per block
    size_t base = (size_t)blockIdx.x * 4096;
    size_t lim = (size_t)NP * 32;
    ull* dst = reinterpret_cast<ull*>(d_ha);
#pragma unroll
    for (int g = 0; g < 4096; g += 128) {
        size_t o = base + g + t;
        if (o < lim) {
            int r = (g + t) >> 5, c = (g + t) & 31;
            dst[o] = sh[r * 33 + c];
        }
    }
}

// ---------------- pass 2: warp/pillar single sweep: sum(h), max(a); then pm + relu ----------------
__global__ __launch_bounds__(256) void k_pillar(float* __restrict__ out) {
    __shared__ float sWb[32 * 32];           // W2b (4 KB)
    __shared__ float shm[8][32];

    int t = threadIdx.x;
    for (int q = t; q < 1024; q += 256) sWb[q] = d_W2f[(q >> 5) * 32 + 1024 + (q & 31)];
    __syncthreads();

    int warp = t >> 5;
    int j = t & 31;
    int p = blockIdx.x * 8 + warp;                 // 3750 * 8 == 30000 exact
    int off = d_offset[p];
    int cnt = d_count[p];
    if (cnt == 0) { out[p * 32 + j] = 0.f; return; }
    const int* ip = d_idx + off;

    float s0 = 0.f, s1 = 0.f, s2 = 0.f, s3 = 0.f;
    float m0 = -1e30f, m1 = -1e30f, m2 = -1e30f, m3 = -1e30f;
    for (int rb = 0; rb < cnt; rb += 32) {
        int lim = min(32, cnt - rb);
        int myidx = (j < lim) ? ip[rb + j] : 0;
        int u = 0;
        for (; u + 4 <= lim; u += 4) {
            int r0 = __shfl_sync(0xffffffffu, myidx, u + 0);
            int r1 = __shfl_sync(0xffffffffu, myidx, u + 1);
            int r2 = __shfl_sync(0xffffffffu, myidx, u + 2);
            int r3 = __shfl_sync(0xffffffffu, myidx, u + 3);
            const float* b0 = &d_ha[(size_t)r0 * 64 + j];
            const float* b1 = &d_ha[(size_t)r1 * 64 + j];
            const float* b2 = &d_ha[(size_t)r2 * 64 + j];
            const float* b3 = &d_ha[(size_t)r3 * 64 + j];
            float h0 = b0[0], a0 = b0[32];
            float h1 = b1[0], a1 = b1[32];
            float h2 = b2[0], a2 = b2[32];
            float h3 = b3[0], a3 = b3[32];
            s0 += h0; m0 = fmaxf(m0, a0);
            s1 += h1; m1 = fmaxf(m1, a1);
            s2 += h2; m2 = fmaxf(m2, a2);
            s3 += h3; m3 = fmaxf(m3, a3);
        }
        for (; u < lim; u++) {
            int r0 = __shfl_sync(0xffffffffu, myidx, u);
            const float* b0 = &d_ha[(size_t)r0 * 64 + j];
            s0 += b0[0];
            m0 = fmaxf(m0, b0[32]);
        }
    }
    float mean = ((s0 + s1) + (s2 + s3)) / (float)cnt;
    float maxa = fmaxf(fmaxf(m0, m1), fmaxf(m2, m3));

    // pm_j = mean . W2b[:,j]  (t2 already folded into a)
    shm[warp][j] = mean;
    __syncwarp();
    float pm = 0.f;
#pragma unroll
    for (int k = 0; k < 32; k++) pm = fmaf(shm[warp][k], sWb[k * 32 + j], pm);
    out[p * 32 + j] = fmaxf(maxa + pm, 0.f);
}

// ---------------- launch ----------------
extern "C" void kernel_launch(void* const* d_in, const int* in_sizes, int n_in,
                              void* d_out, int out_size) {
    const float* points   = (const float*)d_in[0];
    const float* f_center = (const float*)d_in[1];
    const int*   unq      = (const int*)d_in[2];
    const float* W1 = (const float*)d_in[3];
    const float* g1 = (const float*)d_in[4];
    const float* b1 = (const float*)d_in[5];
    const float* m1 = (const float*)d_in[6];
    const float* v1 = (const float*)d_in[7];
    const float* W2 = (const float*)d_in[8];
    const float* g2 = (const float*)d_in[9];
    const float* b2 = (const float*)d_in[10];
    const float* m2 = (const float*)d_in[11];
    const float* v2 = (const float*)d_in[12];

    k_init<<<(NPIL + 255) / 256, 256>>>(W1, g1, b1, m1, v1, W2, g2, b2, m2, v2);
    k_hist<<<(NP / 4 + 255) / 256, 256>>>(unq);
    k_alloc<<<(NPIL + 255) / 256, 256>>>();
    k_sidx<<<(NP / 4 + 255) / 256, 256>>>(unq);
    k_pass1<<<(NP + 127) / 128, 128>>>(points, f_center);
    k_pillar<<<NPIL / 8, 256>>>((float*)d_out);
}

// round 7
// speedup vs baseline: 1.7069x; 1.2024x over previous
#include <cuda_runtime.h>
#include <cuda_fp16.h>

#define NP 1000000
#define NPIL 30000

typedef unsigned long long ull;

__device__ __forceinline__ ull pack2(float lo, float hi) {
    ull r; asm("mov.b64 %0,{%1,%2};" : "=l"(r) : "f"(lo), "f"(hi)); return r;
}
__device__ __forceinline__ void unpack2(ull v, float& lo, float& hi) {
    asm("mov.b64 {%0,%1},%2;" : "=f"(lo), "=f"(hi) : "l"(v));
}
__device__ __forceinline__ ull ffma2(ull a, ull b, ull c) {
    ull d; asm("fma.rn.f32x2 %0,%1,%2,%3;" : "=l"(d) : "l"(a), "l"(b), "l"(c)); return d;
}

// ---------------- scratch ----------------
__device__ float d_W1f[7 * 32];
__device__ float d_t1[32];
__device__ float d_W2f[64 * 32];
__device__ float d_t2[32];
__device__ int   d_count[NPIL];
__device__ int   d_offset[NPIL];
__device__ int   d_galloc;
__device__ int   d_pos[NP];                              // rank of point within its pillar
__device__ int   d_idx[NP];                              // pillar-grouped point indices
__device__ __align__(16) unsigned int d_ha[(size_t)NP * 32];  // fp16 [h(32)|a(32)] = 128B/row

// ---------------- init: zero counters + fold BN into weights ----------------
__global__ void k_init(const float* __restrict__ W1, const float* __restrict__ g1,
                       const float* __restrict__ b1, const float* __restrict__ m1,
                       const float* __restrict__ v1, const float* __restrict__ W2,
                       const float* __restrict__ g2, const float* __restrict__ b2,
                       const float* __restrict__ m2, const float* __restrict__ v2) {
    int i = blockIdx.x * blockDim.x + threadIdx.x;
    if (i < NPIL) d_count[i] = 0;
    if (i == 0) d_galloc = 0;
    if (blockIdx.x == 0 && threadIdx.x < 32) {
        int j = threadIdx.x;
        float s1 = g1[j] * rsqrtf(v1[j] + 1e-3f);
        d_t1[j] = b1[j] - m1[j] * s1;
        for (int k = 0; k < 7; k++) d_W1f[k * 32 + j] = W1[k * 32 + j] * s1;
        float s2 = g2[j] * rsqrtf(v2[j] + 1e-3f);
        d_t2[j] = b2[j] - m2[j] * s2;
        for (int k = 0; k < 64; k++) d_W2f[k * 32 + j] = W2[k * 32 + j] * s2;
    }
}

// ---------------- histogram + per-point rank (int4 vectorized) ----------------
__global__ void k_hist(const int* __restrict__ unq) {
    int i = blockIdx.x * blockDim.x + threadIdx.x;
    if (i < NP / 4) {
        int4 v = ((const int4*)unq)[i];
        int4 r;
        r.x = atomicAdd(&d_count[v.x], 1);
        r.y = atomicAdd(&d_count[v.y], 1);
        r.z = atomicAdd(&d_count[v.z], 1);
        r.w = atomicAdd(&d_count[v.w], 1);
        ((int4*)d_pos)[i] = r;
    }
}

// ---------------- segment allocation: block scan + one global atomic per block ----------------
__global__ __launch_bounds__(256) void k_alloc() {
    __shared__ int wsum[8], wpre[8], sbase;
    int t = threadIdx.x, lane = t & 31, w = t >> 5;
    int i = blockIdx.x * 256 + t;
    int c = (i < NPIL) ? d_count[i] : 0;
    int incl = c;
#pragma unroll
    for (int d = 1; d < 32; d <<= 1) {
        int v = __shfl_up_sync(0xffffffffu, incl, d);
        if (lane >= d) incl += v;
    }
    if (lane == 31) wsum[w] = incl;
    __syncthreads();
    if (w == 0 && lane < 8) {
        int s = wsum[lane];
        int inc = s;
#pragma unroll
        for (int d = 1; d < 8; d <<= 1) {
            int v = __shfl_up_sync(0xffu, inc, d);
            if (lane >= d) inc += v;
        }
        wpre[lane] = inc - s;
        if (lane == 7) sbase = atomicAdd(&d_galloc, inc);
    }
    __syncthreads();
    if (i < NPIL) d_offset[i] = sbase + wpre[w] + (incl - c);
}

// ---------------- pass 1: h = relu(feat@W1f+t1); a = h@W2a + t2; fp16 [h|a] coalesced;
//                  also scatters the sorted point index (fused k_sidx) ----------------
__global__ __launch_bounds__(128) void k_pass1(const float* __restrict__ pts,
                                               const float* __restrict__ fc,
                                               const int* __restrict__ unq) {
    __shared__ ull swp[112];             // W1f packed pairs (7 x 16)
    __shared__ ull st1[16];
    __shared__ ulonglong2 swa[256];      // W2a packed pairs (32 rows x 8 u2), 4 KB
    __shared__ ull st2[16];
    __shared__ ull sh[128 * 17];         // fp16 staging: 16-ull rows, stride 17 (17.4 KB)
    int t = threadIdx.x;
    if (t < 112) { float2 w = ((const float2*)d_W1f)[t]; swp[t] = pack2(w.x, w.y); }
    for (int q = t; q < 256; q += 128) {
        float4 w = ((const float4*)d_W2f)[q];
        swa[q].x = pack2(w.x, w.y);
        swa[q].y = pack2(w.z, w.w);
    }
    if (t < 16) { float2 v = ((const float2*)d_t1)[t]; st1[t] = pack2(v.x, v.y); }
    else if (t < 32) { float2 v = ((const float2*)d_t2)[t - 16]; st2[t - 16] = pack2(v.x, v.y); }
    __syncthreads();

    int i = blockIdx.x * 128 + t;
    if (i < NP) {
        // fused index scatter (was k_sidx)
        d_idx[d_offset[unq[i]] + d_pos[i]] = i;

        float f[7];
        f[0] = fc[i * 3 + 0];
        f[1] = fc[i * 3 + 1];
        f[2] = fc[i * 3 + 2];
        f[3] = pts[i * 5 + 1];
        f[4] = pts[i * 5 + 2];
        f[5] = pts[i * 5 + 3];
        f[6] = pts[i * 5 + 4];

        // h = feat @ W1f + t1 (packed)
        ull h2[16];
#pragma unroll
        for (int j = 0; j < 16; j++) h2[j] = st1[j];
#pragma unroll
        for (int k = 0; k < 7; k++) {
            ull fk = pack2(f[k], f[k]);
#pragma unroll
            for (int j = 0; j < 16; j++) h2[j] = ffma2(swp[k * 16 + j], fk, h2[j]);
        }
        // relu -> scalar h
        float hr[32];
#pragma unroll
        for (int j = 0; j < 16; j++) {
            float lo, hi;
            unpack2(h2[j], lo, hi);
            hr[2 * j] = fmaxf(lo, 0.f);
            hr[2 * j + 1] = fmaxf(hi, 0.f);
        }
        // a = h @ W2a + t2 (packed, LDS.128 broadcast weights)
        ull a2[16];
#pragma unroll
        for (int j = 0; j < 16; j++) a2[j] = st2[j];
#pragma unroll
        for (int k = 0; k < 32; k++) {
            ull fk = pack2(hr[k], hr[k]);
            const ulonglong2* wr = &swa[k * 8];
#pragma unroll
            for (int j2 = 0; j2 < 8; j2++) {
                ulonglong2 w = wr[j2];
                a2[2 * j2 + 0] = ffma2(w.x, fk, a2[2 * j2 + 0]);
                a2[2 * j2 + 1] = ffma2(w.y, fk, a2[2 * j2 + 1]);
            }
        }
        // stage fp16 row: words 0-15 = h pairs, 16-31 = a pairs (2 half2 per ull)
        ull* myrow = &sh[t * 17];
#pragma unroll
        for (int q = 0; q < 8; q++) {
            __half2 p0 = __floats2half2_rn(hr[4 * q + 0], hr[4 * q + 1]);
            __half2 p1 = __floats2half2_rn(hr[4 * q + 2], hr[4 * q + 3]);
            unsigned int u0 = *reinterpret_cast<unsigned int*>(&p0);
            unsigned int u1 = *reinterpret_cast<unsigned int*>(&p1);
            myrow[q] = ((ull)u1 << 32) | u0;
        }
#pragma unroll
        for (int q = 0; q < 8; q++) {
            float x0, x1, x2, x3;
            unpack2(a2[2 * q + 0], x0, x1);
            unpack2(a2[2 * q + 1], x2, x3);
            __half2 p0 = __floats2half2_rn(x0, x1);
            __half2 p1 = __floats2half2_rn(x2, x3);
            unsigned int u0 = *reinterpret_cast<unsigned int*>(&p0);
            unsigned int u1 = *reinterpret_cast<unsigned int*>(&p1);
            myrow[8 + q] = ((ull)u1 << 32) | u0;
        }
    }
    __syncthreads();

    // coalesced copy-out: 128 rows x 16 ulls = 2048 ulls per block
    size_t base = (size_t)blockIdx.x * 2048;
    size_t lim = (size_t)NP * 16;
    ull* dst = reinterpret_cast<ull*>(d_ha);
#pragma unroll
    for (int g = 0; g < 2048; g += 128) {
        size_t o = base + g + t;
        if (o < lim) {
            int r = (g + t) >> 4, c = (g + t) & 15;
            dst[o] = sh[r * 17 + c];
        }
    }
}

// ---------------- pass 2: warp/pillar single sweep over fp16 rows (1 LDG/lane/row) ----------
__global__ __launch_bounds__(256) void k_pillar(float* __restrict__ out) {
    __shared__ float sWb[32 * 32];           // W2b (4 KB)
    __shared__ float ssum[8][32];
    __shared__ float smax[8][32];

    int t = threadIdx.x;
    for (int q = t; q < 1024; q += 256) sWb[q] = d_W2f[1024 + q];
    __syncthreads();

    int warp = t >> 5;
    int j = t & 31;
    int p = blockIdx.x * 8 + warp;                 // 3750 * 8 == 30000 exact
    int off = d_offset[p];
    int cnt = d_count[p];
    if (cnt == 0) { out[p * 32 + j] = 0.f; return; }
    const int* ip = d_idx + off;
    const unsigned int* ha = d_ha;

    // lane j reads word j of each 128B row: j<16 -> h pair j, j>=16 -> a pair (j-16)
    float sx0 = 0.f, sy0 = 0.f, sx1 = 0.f, sy1 = 0.f;
    float mx = -1e30f, my = -1e30f;
    for (int rb = 0; rb < cnt; rb += 32) {
        int lim = min(32, cnt - rb);
        int myidx = (j < lim) ? ip[rb + j] : 0;
        int u = 0;
        for (; u + 4 <= lim; u += 4) {
            int r0 = __shfl_sync(0xffffffffu, myidx, u + 0);
            int r1 = __shfl_sync(0xffffffffu, myidx, u + 1);
            int r2 = __shfl_sync(0xffffffffu, myidx, u + 2);
            int r3 = __shfl_sync(0xffffffffu, myidx, u + 3);
            unsigned int w0 = ha[(size_t)r0 * 32 + j];
            unsigned int w1 = ha[(size_t)r1 * 32 + j];
            unsigned int w2 = ha[(size_t)r2 * 32 + j];
            unsigned int w3 = ha[(size_t)r3 * 32 + j];
            float2 f0 = __half22float2(*reinterpret_cast<__half2*>(&w0));
            float2 f1 = __half22float2(*reinterpret_cast<__half2*>(&w1));
            float2 f2 = __half22float2(*reinterpret_cast<__half2*>(&w2));
            float2 f3 = __half22float2(*reinterpret_cast<__half2*>(&w3));
            sx0 += f0.x; sy0 += f0.y; mx = fmaxf(mx, f0.x); my = fmaxf(my, f0.y);
            sx1 += f1.x; sy1 += f1.y; mx = fmaxf(mx, f1.x); my = fmaxf(my, f1.y);
            sx0 += f2.x; sy0 += f2.y; mx = fmaxf(mx, f2.x); my = fmaxf(my, f2.y);
            sx1 += f3.x; sy1 += f3.y; mx = fmaxf(mx, f3.x); my = fmaxf(my, f3.y);
        }
        for (; u < lim; u++) {
            int r0 = __shfl_sync(0xffffffffu, myidx, u);
            unsigned int w0 = ha[(size_t)r0 * 32 + j];
            float2 f0 = __half22float2(*reinterpret_cast<__half2*>(&w0));
            sx0 += f0.x; sy0 += f0.y; mx = fmaxf(mx, f0.x); my = fmaxf(my, f0.y);
        }
    }
    // lanes 0-15: channel sums (2j, 2j+1);  lanes 16-31: channel maxes (2(j-16), ...)
    if (j < 16) {
        ssum[warp][2 * j + 0] = sx0 + sx1;
        ssum[warp][2 * j + 1] = sy0 + sy1;
    } else {
        smax[warp][2 * (j - 16) + 0] = mx;
        smax[warp][2 * (j - 16) + 1] = my;
    }
    __syncwarp();

    // pm_j = (sum_h . W2b[:,j]) / cnt   (t2 already folded into a)
    float pm = 0.f;
#pragma unroll
    for (int k = 0; k < 32; k++) pm = fmaf(ssum[warp][k], sWb[k * 32 + j], pm);
    pm /= (float)cnt;
    out[p * 32 + j] = fmaxf(smax[warp][j] + pm, 0.f);
}

// ---------------- launch ----------------
extern "C" void kernel_launch(void* const* d_in, const int* in_sizes, int n_in,
                              void* d_out, int out_size) {
    const float* points   = (const float*)d_in[0];
    const float* f_center = (const float*)d_in[1];
    const int*   unq      = (const int*)d_in[2];
    const float* W1 = (const float*)d_in[3];
    const float* g1 = (const float*)d_in[4];
    const float* b1 = (const float*)d_in[5];
    const float* m1 = (const float*)d_in[6];
    const float* v1 = (const float*)d_in[7];
    const float* W2 = (const float*)d_in[8];
    const float* g2 = (const float*)d_in[9];
    const float* b2 = (const float*)d_in[10];
    const float* m2 = (const float*)d_in[11];
    const float* v2 = (const float*)d_in[12];

    k_init<<<(NPIL + 255) / 256, 256>>>(W1, g1, b1, m1, v1, W2, g2, b2, m2, v2);
    k_hist<<<(NP / 4 + 255) / 256, 256>>>(unq);
    k_alloc<<<(NPIL + 255) / 256, 256>>>();
    k_pass1<<<(NP + 127) / 128, 128>>>(points, f_center, unq);
    k_pillar<<<NPIL / 8, 256>>>((float*)d_out);
}

// round 8
// speedup vs baseline: 2.1830x; 1.2790x over previous
#include <cuda_runtime.h>
#include <cuda_fp16.h>

#define NP 1000000
#define NPIL 30000

typedef unsigned long long ull;
typedef unsigned int u32;

__device__ __forceinline__ ull pack2(float lo, float hi) {
    ull r; asm("mov.b64 %0,{%1,%2};" : "=l"(r) : "f"(lo), "f"(hi)); return r;
}
__device__ __forceinline__ void unpack2(ull v, float& lo, float& hi) {
    asm("mov.b64 {%0,%1},%2;" : "=f"(lo), "=f"(hi) : "l"(v));
}
__device__ __forceinline__ ull ffma2(ull a, ull b, ull c) {
    ull d; asm("fma.rn.f32x2 %0,%1,%2,%3;" : "=l"(d) : "l"(a), "l"(b), "l"(c)); return d;
}
__device__ __forceinline__ u32 s2u(const void* p) {
    return (u32)__cvta_generic_to_shared(p);
}
__device__ __forceinline__ u32 h2bits(__half2 v) {
    u32 b; asm("mov.b32 %0,%1;" : "=r"(b) : "r"(*(u32*)&v)); return *(u32*)&v; (void)b;
}

// ---------------- scratch ----------------
__device__ float d_W1f[7 * 32];
__device__ float d_t1[32];
__device__ float d_W2f[64 * 32];
__device__ float d_t2[32];
__device__ __half d_W2ah[32 * 32];     // folded W2a, TRANSPOSED: [n][k] fp16
__device__ int   d_count[NPIL];
__device__ int   d_offset[NPIL];
__device__ int   d_galloc;
__device__ int   d_pos[NP];
__device__ int   d_idx[NP];
__device__ __align__(16) u32 d_ha[(size_t)NP * 32];  // fp16 [h(32)|a(32)] = 128B/row

// ---------------- init ----------------
__global__ void k_init(const float* __restrict__ W1, const float* __restrict__ g1,
                       const float* __restrict__ b1, const float* __restrict__ m1,
                       const float* __restrict__ v1, const float* __restrict__ W2,
                       const float* __restrict__ g2, const float* __restrict__ b2,
                       const float* __restrict__ m2, const float* __restrict__ v2) {
    int i = blockIdx.x * blockDim.x + threadIdx.x;
    if (i < NPIL) d_count[i] = 0;
    if (i == 0) d_galloc = 0;
    if (blockIdx.x == 0 && threadIdx.x < 32) {
        int j = threadIdx.x;
        float s1 = g1[j] * rsqrtf(v1[j] + 1e-3f);
        d_t1[j] = b1[j] - m1[j] * s1;
        for (int k = 0; k < 7; k++) d_W1f[k * 32 + j] = W1[k * 32 + j] * s1;
        float s2 = g2[j] * rsqrtf(v2[j] + 1e-3f);
        d_t2[j] = b2[j] - m2[j] * s2;
        for (int k = 0; k < 64; k++) d_W2f[k * 32 + j] = W2[k * 32 + j] * s2;
        for (int k = 0; k < 32; k++)             // [n=j][k] transposed fp16 W2a
            d_W2ah[j * 32 + k] = __float2half(W2[k * 32 + j] * s2);
    }
}

// ---------------- histogram + per-point rank ----------------
__global__ void k_hist(const int* __restrict__ unq) {
    int i = blockIdx.x * blockDim.x + threadIdx.x;
    if (i < NP / 4) {
        int4 v = ((const int4*)unq)[i];
        int4 r;
        r.x = atomicAdd(&d_count[v.x], 1);
        r.y = atomicAdd(&d_count[v.y], 1);
        r.z = atomicAdd(&d_count[v.z], 1);
        r.w = atomicAdd(&d_count[v.w], 1);
        ((int4*)d_pos)[i] = r;
    }
}

// ---------------- segment allocation ----------------
__global__ __launch_bounds__(256) void k_alloc() {
    __shared__ int wsum[8], wpre[8], sbase;
    int t = threadIdx.x, lane = t & 31, w = t >> 5;
    int i = blockIdx.x * 256 + t;
    int c = (i < NPIL) ? d_count[i] : 0;
    int incl = c;
#pragma unroll
    for (int d = 1; d < 32; d <<= 1) {
        int v = __shfl_up_sync(0xffffffffu, incl, d);
        if (lane >= d) incl += v;
    }
    if (lane == 31) wsum[w] = incl;
    __syncthreads();
    if (w == 0 && lane < 8) {
        int s = wsum[lane];
        int inc = s;
#pragma unroll
        for (int d = 1; d < 8; d <<= 1) {
            int v = __shfl_up_sync(0xffu, inc, d);
            if (lane >= d) inc += v;
        }
        wpre[lane] = inc - s;
        if (lane == 7) sbase = atomicAdd(&d_galloc, inc);
    }
    __syncthreads();
    if (i < NPIL) d_offset[i] = sbase + wpre[w] + (incl - c);
}

// ---------------- pass 1: scalar h, tensor-core a, coalesced [h|a] fp16 store ----------------
// staging row per point: 72 halves = [h(32) | a(32) | pad(8)], stride 144B.
// 144B row stride => ldmatrix 8-row reads hit 8 distinct 16B granules (9 mod 8 walk).
__global__ __launch_bounds__(128) void k_pass1(const float* __restrict__ pts,
                                               const float* __restrict__ fc,
                                               const int* __restrict__ unq) {
    __shared__ ull swp[112];                 // W1f packed pairs
    __shared__ ull st1[16];
    __shared__ __half sWa[32 * 40];          // [n][k] fp16, stride 40 halves
    __shared__ float sT2[32];
    __shared__ __align__(16) __half sh[128 * 72];   // 18 KB staging
    int t = threadIdx.x;
    if (t < 112) { float2 w = ((const float2*)d_W1f)[t]; swp[t] = pack2(w.x, w.y); }
    if (t < 16)  { float2 v = ((const float2*)d_t1)[t];  st1[t] = pack2(v.x, v.y); }
    for (int q = t; q < 1024; q += 128) sWa[(q >> 5) * 40 + (q & 31)] = d_W2ah[q];
    if (t < 32) sT2[t] = d_t2[t];
    __syncthreads();

    int lane = t & 31, wid = t >> 5;
    int i = blockIdx.x * 128 + t;
    int ic = min(i, NP - 1);

    if (i < NP) d_idx[d_offset[unq[i]] + d_pos[i]] = i;   // fused index scatter

    // ---- scalar h = relu(feat @ W1f + t1), fp32 exact, f32x2 packed ----
    float f[7];
    f[0] = fc[ic * 3 + 0];
    f[1] = fc[ic * 3 + 1];
    f[2] = fc[ic * 3 + 2];
    f[3] = pts[ic * 5 + 1];
    f[4] = pts[ic * 5 + 2];
    f[5] = pts[ic * 5 + 3];
    f[6] = pts[ic * 5 + 4];
    ull h2[16];
#pragma unroll
    for (int j = 0; j < 16; j++) h2[j] = st1[j];
#pragma unroll
    for (int k = 0; k < 7; k++) {
        ull fk = pack2(f[k], f[k]);
#pragma unroll
        for (int j = 0; j < 16; j++) h2[j] = ffma2(swp[k * 16 + j], fk, h2[j]);
    }
    // relu -> fp16 -> stage halves 0..31 of this point's row
    u32* mr32 = reinterpret_cast<u32*>(&sh[t * 72]);
#pragma unroll
    for (int q = 0; q < 16; q++) {
        float lo, hi;
        unpack2(h2[q], lo, hi);
        __half2 p = __floats2half2_rn(fmaxf(lo, 0.f), fmaxf(hi, 0.f));
        mr32[q] = *reinterpret_cast<u32*>(&p);
    }
    __syncwarp();

    // ---- B fragments: W2a fp16 [n][k], once per warp ----
    u32 bfr[4][2][2];
    u32 wb = s2u(sWa);
#pragma unroll
    for (int nt = 0; nt < 4; nt++)
#pragma unroll
        for (int q = 0; q < 2; q++) {
            u32 addr = wb + (((nt * 8 + (lane & 7)) * 40 + q * 16 + ((lane & 8) ? 8 : 0)) << 1);
            asm volatile("ldmatrix.sync.aligned.m8n8.x2.shared.b16 {%0,%1},[%2];"
                         : "=r"(bfr[nt][q][0]), "=r"(bfr[nt][q][1]) : "r"(addr));
        }
    float t2lo[4], t2hi[4];
#pragma unroll
    for (int nt = 0; nt < 4; nt++) {
        t2lo[nt] = sT2[nt * 8 + 2 * (lane & 3)];
        t2hi[nt] = sT2[nt * 8 + 2 * (lane & 3) + 1];
    }

    // ---- tensor-core a = h @ W2a + t2 for this warp's 32 points ----
    u32 shb = s2u(sh);
#pragma unroll
    for (int tile = 0; tile < 2; tile++) {
        int p0 = wid * 32 + tile * 16;
        u32 a[2][4];
#pragma unroll
        for (int q = 0; q < 2; q++) {
            int r = p0 + (lane & 7) + ((lane & 8) ? 8 : 0);
            int colh = q * 16 + ((lane & 16) ? 8 : 0);
            u32 addr = shb + ((r * 72 + colh) << 1);
            asm volatile("ldmatrix.sync.aligned.m8n8.x4.shared.b16 {%0,%1,%2,%3},[%4];"
                         : "=r"(a[q][0]), "=r"(a[q][1]), "=r"(a[q][2]), "=r"(a[q][3])
                         : "r"(addr));
        }
#pragma unroll
        for (int nt = 0; nt < 4; nt++) {
            float d0 = 0.f, d1 = 0.f, d2 = 0.f, d3 = 0.f;
            asm volatile("mma.sync.aligned.m16n8k16.row.col.f32.f16.f16.f32 "
                         "{%0,%1,%2,%3},{%4,%5,%6,%7},{%8,%9},{%0,%1,%2,%3};"
                         : "+f"(d0), "+f"(d1), "+f"(d2), "+f"(d3)
                         : "r"(a[0][0]), "r"(a[0][1]), "r"(a[0][2]), "r"(a[0][3]),
                           "r"(bfr[nt][0][0]), "r"(bfr[nt][0][1]));
            asm volatile("mma.sync.aligned.m16n8k16.row.col.f32.f16.f16.f32 "
                         "{%0,%1,%2,%3},{%4,%5,%6,%7},{%8,%9},{%0,%1,%2,%3};"
                         : "+f"(d0), "+f"(d1), "+f"(d2), "+f"(d3)
                         : "r"(a[1][0]), "r"(a[1][1]), "r"(a[1][2]), "r"(a[1][3]),
                           "r"(bfr[nt][1][0]), "r"(bfr[nt][1][1]));
            int c0 = nt * 8 + 2 * (lane & 3);
            __half2 plo = __floats2half2_rn(d0 + t2lo[nt], d1 + t2hi[nt]);
            __half2 phi = __floats2half2_rn(d2 + t2lo[nt], d3 + t2hi[nt]);
            *reinterpret_cast<u32*>(&sh[(p0 + (lane >> 2)) * 72 + 32 + c0]) =
                *reinterpret_cast<u32*>(&plo);
            *reinterpret_cast<u32*>(&sh[(p0 + 8 + (lane >> 2)) * 72 + 32 + c0]) =
                *reinterpret_cast<u32*>(&phi);
        }
    }
    __syncthreads();

    // ---- coalesced copy-out: 128 rows x 16 u64 ([h|a] contiguous in staging row) ----
    const ull* src = reinterpret_cast<const ull*>(sh);
    ulonglong2* dst = reinterpret_cast<ulonglong2*>(d_ha);
    size_t b128 = (size_t)blockIdx.x * 1024;         // u128 units (8 per row)
#pragma unroll
    for (int g = 0; g < 1024; g += 128) {
        int e = g + t;
        size_t o = b128 + e;
        if (o < (size_t)NP * 8) {
            int p = e >> 3, w = (e & 7) * 2;
            dst[o] = *reinterpret_cast<const ulonglong2*>(&src[p * 18 + w]);
        }
    }
}

// ---------------- pass 2: warp/pillar single sweep over fp16 rows ----------------
__global__ __launch_bounds__(256) void k_pillar(float* __restrict__ out) {
    __shared__ float sWb[32 * 32];
    __shared__ float ssum[8][32];
    __shared__ float smax[8][32];

    int t = threadIdx.x;
    for (int q = t; q < 1024; q += 256) sWb[q] = d_W2f[1024 + q];
    __syncthreads();

    int warp = t >> 5;
    int j = t & 31;
    int p = blockIdx.x * 8 + warp;
    int off = d_offset[p];
    int cnt = d_count[p];
    if (cnt == 0) { out[p * 32 + j] = 0.f; return; }
    const int* ip = d_idx + off;
    const u32* ha = d_ha;

    float sx0 = 0.f, sy0 = 0.f, sx1 = 0.f, sy1 = 0.f;
    float mx = -1e30f, my = -1e30f;
    for (int rb = 0; rb < cnt; rb += 32) {
        int lim = min(32, cnt - rb);
        int myidx = (j < lim) ? ip[rb + j] : 0;
        int u = 0;
        for (; u + 4 <= lim; u += 4) {
            int r0 = __shfl_sync(0xffffffffu, myidx, u + 0);
            int r1 = __shfl_sync(0xffffffffu, myidx, u + 1);
            int r2 = __shfl_sync(0xffffffffu, myidx, u + 2);
            int r3 = __shfl_sync(0xffffffffu, myidx, u + 3);
            u32 w0 = ha[(size_t)r0 * 32 + j];
            u32 w1 = ha[(size_t)r1 * 32 + j];
            u32 w2 = ha[(size_t)r2 * 32 + j];
            u32 w3 = ha[(size_t)r3 * 32 + j];
            float2 f0 = __half22float2(*reinterpret_cast<__half2*>(&w0));
            float2 f1 = __half22float2(*reinterpret_cast<__half2*>(&w1));
            float2 f2 = __half22float2(*reinterpret_cast<__half2*>(&w2));
            float2 f3 = __half22float2(*reinterpret_cast<__half2*>(&w3));
            sx0 += f0.x; sy0 += f0.y; mx = fmaxf(mx, f0.x); my = fmaxf(my, f0.y);
            sx1 += f1.x; sy1 += f1.y; mx = fmaxf(mx, f1.x); my = fmaxf(my, f1.y);
            sx0 += f2.x; sy0 += f2.y; mx = fmaxf(mx, f2.x); my = fmaxf(my, f2.y);
            sx1 += f3.x; sy1 += f3.y; mx = fmaxf(mx, f3.x); my = fmaxf(my, f3.y);
        }
        for (; u < lim; u++) {
            int r0 = __shfl_sync(0xffffffffu, myidx, u);
            u32 w0 = ha[(size_t)r0 * 32 + j];
            float2 f0 = __half22float2(*reinterpret_cast<__half2*>(&w0));
            sx0 += f0.x; sy0 += f0.y; mx = fmaxf(mx, f0.x); my = fmaxf(my, f0.y);
        }
    }
    if (j < 16) {
        ssum[warp][2 * j + 0] = sx0 + sx1;
        ssum[warp][2 * j + 1] = sy0 + sy1;
    } else {
        smax[warp][2 * (j - 16) + 0] = mx;
        smax[warp][2 * (j - 16) + 1] = my;
    }
    __syncwarp();

    float pm = 0.f;
#pragma unroll
    for (int k = 0; k < 32; k++) pm = fmaf(ssum[warp][k], sWb[k * 32 + j], pm);
    pm /= (float)cnt;
    out[p * 32 + j] = fmaxf(smax[warp][j] + pm, 0.f);
}

// ---------------- launch ----------------
extern "C" void kernel_launch(void* const* d_in, const int* in_sizes, int n_in,
                              void* d_out, int out_size) {
    const float* points   = (const float*)d_in[0];
    const float* f_center = (const float*)d_in[1];
    const int*   unq      = (const int*)d_in[2];
    const float* W1 = (const float*)d_in[3];
    const float* g1 = (const float*)d_in[4];
    const float* b1 = (const float*)d_in[5];
    const float* m1 = (const float*)d_in[6];
    const float* v1 = (const float*)d_in[7];
    const float* W2 = (const float*)d_in[8];
    const float* g2 = (const float*)d_in[9];
    const float* b2 = (const float*)d_in[10];
    const float* m2 = (const float*)d_in[11];
    const float* v2 = (const float*)d_in[12];

    k_init<<<(NPIL + 255) / 256, 256>>>(W1, g1, b1, m1, v1, W2, g2, b2, m2, v2);
    k_hist<<<(NP / 4 + 255) / 256, 256>>>(unq);
    k_alloc<<<(NPIL + 255) / 256, 256>>>();
    k_pass1<<<(NP + 127) / 128, 128>>>(points, f_center, unq);
    k_pillar<<<NPIL / 8, 256>>>((float*)d_out);
}